// round 6
// baseline (speedup 1.0000x reference)
#include <cuda_runtime.h>
#include <cstdint>

#define CRF_S 512
#define CRF_B 256
#define CRF_L 128
#define PAD_ID 0
#define START_ID 1

typedef unsigned long long ull;

// mask dtype: 0 = int32, 1 = byte(bool/int8), 2 = float32
__device__ int g_mode;

// ---------------------------------------------------------------------------
__global__ void crf_prep(const unsigned* __restrict__ masks_w, float* out) {
    __shared__ int flagByte, flagFloat;
    int tid = threadIdx.x;
    if (tid == 0) { flagByte = 0; flagFloat = 0; out[0] = 0.0f; }
    __syncthreads();
    int lb = 0, lf = 0;
    for (int k = tid; k < (CRF_B * CRF_S) / 4; k += blockDim.x) {
        unsigned w = masks_w[k];
        if (w == 0x3F800000u) lf = 1;
        else if (w > 1u) lb = 1;
    }
    if (lb) atomicOr(&flagByte, 1);
    if (lf) atomicOr(&flagFloat, 1);
    __syncthreads();
    if (tid == 0) g_mode = flagFloat ? 2 : (flagByte ? 1 : 0);
}

// ---- packed f32x2 helpers ----
__device__ __forceinline__ ull fma2(ull a, ull b, ull c) {
    ull d;
    asm("fma.rn.f32x2 %0, %1, %2, %3;" : "=l"(d) : "l"(a), "l"(b), "l"(c));
    return d;
}
__device__ __forceinline__ ull add2(ull a, ull b) {
    ull d;
    asm("add.rn.f32x2 %0, %1, %2;" : "=l"(d) : "l"(a), "l"(b));
    return d;
}
__device__ __forceinline__ ull pack2(float lo, float hi) {
    ull r; asm("mov.b64 %0, {%1, %2};" : "=l"(r) : "f"(lo), "f"(hi)); return r;
}
__device__ __forceinline__ float2 unpack2(ull v) {
    float2 r; asm("mov.b64 {%0, %1}, %2;" : "=f"(r.x), "=f"(r.y) : "l"(v)); return r;
}

// 64-FMA2 column dot: dot_j = sum_i p[i] * expT[i][j], 4 chains
__device__ __forceinline__ float coldot(const ulonglong2* pb2, const ull* mat) {
    ull a0 = 0, a1 = 0, a2 = 0, a3 = 0;
    #pragma unroll
    for (int k = 0; k < 32; k += 2) {
        ulonglong2 pA = pb2[k];
        ulonglong2 pB = pb2[k + 1];
        a0 = fma2(pA.x, mat[2 * k],     a0);
        a1 = fma2(pA.y, mat[2 * k + 1], a1);
        a2 = fma2(pB.x, mat[2 * k + 2], a2);
        a3 = fma2(pB.y, mat[2 * k + 3], a3);
    }
    a0 = add2(a0, a1); a2 = add2(a2, a3);
    a0 = add2(a0, a2);
    float2 f = unpack2(a0);
    return f.x + f.y;
}

__device__ __forceinline__ int mask_len(const void* masks, int b, int mode, int lane) {
    int cnt = 0;
    if (mode == 1) {
        const unsigned char* mb = (const unsigned char*)masks + (size_t)b * CRF_S;
        for (int k = lane; k < CRF_S; k += 32) cnt += (mb[k] != 0);
    } else if (mode == 2) {
        const float* mf = (const float*)masks + (size_t)b * CRF_S;
        for (int k = lane; k < CRF_S; k += 32) cnt += (mf[k] != 0.0f);
    } else {
        const int* mi = (const int*)masks + (size_t)b * CRF_S;
        for (int k = lane; k < CRF_S; k += 32) cnt += (mi[k] != 0);
    }
    #pragma unroll
    for (int o = 16; o; o >>= 1) cnt += __shfl_xor_sync(0xffffffffu, cnt, o);
    return cnt < 1 ? 1 : cnt;
}

// ---------------------------------------------------------------------------
// 128 blocks x 128 threads; each block services TWO batches (bA, bB) with one
// shared register copy of expT (thread j holds column j, 64 packed f32x2).
// The two forward recurrences are interleaved step-by-step: one __syncthreads
// per step covers both, and batch B's 64-FMA2 dot fills batch A's latency
// bubbles (exp/log/LDS/barrier), doubling useful issue per step.
// Shift = lag-1 fs[0] (logsumexp is shift-exact; drift << 88 so no overflow).
// ---------------------------------------------------------------------------
__global__ void __launch_bounds__(128, 1) crf_main(
    const float* __restrict__ emit,
    const int*   __restrict__ labels,
    const void*  __restrict__ masks,
    const float* __restrict__ T,
    float* out)
{
    __shared__ __align__(16) float sm_p[2][2][CRF_L];   // [batch][buf][i]
    __shared__ float sm_m[2][2];                        // [buf][batch]
    __shared__ float sm_red[2][4];                      // reduction scratch
    __shared__ float sm_acc[2];                         // per-batch (r - gold - ends)

    int gt   = threadIdx.x;         // 0..127 == column j
    int lane = gt & 31;
    int warp = gt >> 5;
    int bA   = blockIdx.x * 2;
    int bB   = bA + 1;

    // ---- expT column j -> 64 packed register pairs (shared by both batches) ----
    ull mat[64];
    #pragma unroll
    for (int k = 0; k < 64; k++) {
        float lo = __expf(T[(2 * k)     * CRF_L + gt]);
        float hi = __expf(T[(2 * k + 1) * CRF_L + gt]);
        mat[k] = pack2(lo, hi);
    }

    // ---- lengths (every warp computes both redundantly; one-time cost) ----
    int mode = g_mode;
    int lenA = mask_len(masks, bA, mode, lane);
    int lenB = mask_len(masks, bB, mode, lane);
    int tmax = lenA > lenB ? lenA : lenB;

    // ---- gold path: warp 0 -> batch A, warp 1 -> batch B ----
    if (warp < 2) {
        int b   = warp ? bB : bA;
        int len = warp ? lenB : lenA;
        float gold = 0.f;
        for (int t = lane; t < len; t += 32) {
            int lab  = labels[b * CRF_S + t];
            int prev = (t == 0) ? START_ID : labels[b * CRF_S + t - 1];
            gold += emit[((size_t)t * CRF_B + b) * CRF_L + lab] + T[prev * CRF_L + lab];
        }
        #pragma unroll
        for (int o = 16; o; o >>= 1) gold += __shfl_xor_sync(0xffffffffu, gold, o);
        if (lane == 0)
            sm_acc[warp] = -(gold + T[labels[b * CRF_S + (len - 1)] * CRF_L + PAD_ID]);
    }

    // ---- init: fs_j = emit[0][b][j] + T[START][j]; shift = fs[0] (lag) ----
    float tstart = T[START_ID * CRF_L + gt];
    float fsA = emit[(size_t)bA * CRF_L + gt] + tstart;
    float fsB = emit[(size_t)bB * CRF_L + gt] + tstart;
    if (gt == 0) { sm_m[0][0] = fsA; sm_m[0][1] = fsB; }
    __syncthreads();
    float mA = sm_m[0][0];
    float mB = sm_m[0][1];

    // ---- emit prefetch pipelines (depth 2) ----
    const long estride = (long)CRF_B * CRF_L;
    const float* epA = emit + estride + (size_t)bA * CRF_L + gt;   // t=1
    const float* epB = emit + estride + (size_t)bB * CRF_L + gt;
    float eAc = 0.f, eAn = 0.f, eBc = 0.f, eBn = 0.f;
    if (lenA > 1) eAc = epA[0];
    if (lenA > 2) eAn = epA[estride];
    if (lenB > 1) eBc = epB[0];
    if (lenB > 2) eBn = epB[estride];

    // ---- interleaved forward scans ----
    int buf = 1;
    for (int t = 1; t < tmax; t++) {
        float pA = __expf(fsA - mA);
        float pB = __expf(fsB - mB);
        sm_p[0][buf][gt] = pA;
        sm_p[1][buf][gt] = pB;
        if (gt == 0) { sm_m[buf][0] = fsA; sm_m[buf][1] = fsB; }

        float eAf = 0.f, eBf = 0.f;
        if (t + 2 < lenA) eAf = epA[2 * estride];
        if (t + 2 < lenB) eBf = epB[2 * estride];

        __syncthreads();

        float mAn = sm_m[buf][0];
        float mBn = sm_m[buf][1];

        // block-uniform predicates -> no divergence, skips work for done chains
        if (t < lenA) {
            float dA = coldot(reinterpret_cast<const ulonglong2*>(sm_p[0][buf]), mat);
            fsA = eAc + mA + __logf(dA);
        }
        if (t < lenB) {
            float dB = coldot(reinterpret_cast<const ulonglong2*>(sm_p[1][buf]), mat);
            fsB = eBc + mB + __logf(dB);
        }

        mA = mAn; mB = mBn;
        eAc = eAn; eAn = eAf;
        eBc = eBn; eBn = eBf;
        epA += estride; epB += estride;
        buf ^= 1;
    }

    // ---- encode per batch: logsumexp_j(fs[j] + T[j][PAD]) ----
    float tpad = T[gt * CRF_L + PAD_ID];
    __syncthreads();   // quiesce last iteration's smem traffic
    #pragma unroll
    for (int sel = 0; sel < 2; sel++) {
        float x = (sel ? fsB : fsA) + tpad;
        float wm = x;
        #pragma unroll
        for (int o = 16; o; o >>= 1) wm = fmaxf(wm, __shfl_xor_sync(0xffffffffu, wm, o));
        if (lane == 0) sm_red[0][warp] = wm;
        __syncthreads();
        float4 wv = *reinterpret_cast<float4*>(sm_red[0]);
        float mm = fmaxf(fmaxf(wv.x, wv.y), fmaxf(wv.z, wv.w));
        float s = __expf(x - mm);
        #pragma unroll
        for (int o = 16; o; o >>= 1) s += __shfl_xor_sync(0xffffffffu, s, o);
        if (lane == 0) sm_red[1][warp] = s;
        __syncthreads();
        if (gt == 0) {
            float4 sv = *reinterpret_cast<float4*>(sm_red[1]);
            sm_acc[sel] += mm + __logf(sv.x + sv.y + sv.z + sv.w);
        }
        __syncthreads();
    }
    if (gt == 0) atomicAdd(out, sm_acc[0] + sm_acc[1]);
}

// ---------------------------------------------------------------------------
extern "C" void kernel_launch(void* const* d_in, const int* in_sizes, int n_in,
                              void* d_out, int out_size) {
    const float* emit   = (const float*)d_in[0];
    const int*   labels = (const int*)d_in[1];
    const void*  masks  = d_in[2];
    const float* T      = (const float*)d_in[3];
    float* out = (float*)d_out;

    (void)in_sizes; (void)n_in; (void)out_size;

    crf_prep<<<1, 256>>>((const unsigned*)masks, out);
    crf_main<<<CRF_B / 2, 128>>>(emit, labels, masks, T, out);
}

// round 9
// speedup vs baseline: 1.6915x; 1.6915x over previous
#include <cuda_runtime.h>
#include <cstdint>

#define CRF_S 512
#define CRF_B 256
#define CRF_L 128
#define PAD_ID 0
#define START_ID 1

typedef unsigned long long ull;

__device__ int g_mode;            // 0 = int32, 1 = byte, 2 = float32
__device__ int g_len[CRF_B];      // per-batch length
__device__ int g_sched[CRF_B];    // batch index sorted by length (ascending)

// ---------------------------------------------------------------------------
// Prep: detect mask dtype, compute all lengths (warp per batch, coalesced),
// rank-sort batches by length, zero output.
// ---------------------------------------------------------------------------
__global__ void crf_prep(const void* __restrict__ masks, float* out) {
    __shared__ int flagByte, flagFloat;
    __shared__ int slen[CRF_B];
    int tid  = threadIdx.x;
    int wid  = tid >> 5;
    int lane = tid & 31;
    if (tid == 0) { flagByte = 0; flagFloat = 0; out[0] = 0.0f; }
    __syncthreads();

    // dtype fingerprint
    const unsigned* mw = (const unsigned*)masks;
    int lb = 0, lf = 0;
    for (int k = tid; k < (CRF_B * CRF_S) / 4; k += 256) {
        unsigned w = mw[k];
        if (w == 0x3F800000u) lf = 1;          // float 1.0 pattern
        else if (w > 1u) lb = 1;               // byte-packed bools
    }
    if (lb) atomicOr(&flagByte, 1);
    if (lf) atomicOr(&flagFloat, 1);
    __syncthreads();
    int mode = flagFloat ? 2 : (flagByte ? 1 : 0);
    if (tid == 0) g_mode = mode;

    // lengths: one warp per batch, lanes stride the row (coalesced)
    for (int b = wid; b < CRF_B; b += 8) {
        int cnt = 0;
        if (mode == 1) {
            const unsigned char* mb = (const unsigned char*)masks + (size_t)b * CRF_S;
            for (int k = lane; k < CRF_S; k += 32) cnt += (mb[k] != 0);
        } else if (mode == 2) {
            const float* mf = (const float*)masks + (size_t)b * CRF_S;
            for (int k = lane; k < CRF_S; k += 32) cnt += (mf[k] != 0.0f);
        } else {
            const int* mi = (const int*)masks + (size_t)b * CRF_S;
            for (int k = lane; k < CRF_S; k += 32) cnt += (mi[k] != 0);
        }
        #pragma unroll
        for (int o = 16; o; o >>= 1) cnt += __shfl_xor_sync(0xffffffffu, cnt, o);
        if (cnt < 1) cnt = 1;
        if (lane == 0) { slen[b] = cnt; g_len[b] = cnt; }
    }
    __syncthreads();

    // rank sort: thread tid ranks batch tid among all (ties by index)
    int mylen = slen[tid];
    int rank = 0;
    for (int j = 0; j < CRF_B; j++) {
        int lj = slen[j];
        rank += (lj < mylen) || (lj == mylen && j < tid);
    }
    g_sched[rank] = tid;
}

// ---- packed f32x2 helpers ----
__device__ __forceinline__ ull fma2(ull a, ull b, ull c) {
    ull d;
    asm("fma.rn.f32x2 %0, %1, %2, %3;" : "=l"(d) : "l"(a), "l"(b), "l"(c));
    return d;
}
__device__ __forceinline__ ull add2(ull a, ull b) {
    ull d;
    asm("add.rn.f32x2 %0, %1, %2;" : "=l"(d) : "l"(a), "l"(b));
    return d;
}
__device__ __forceinline__ ull pack2(float lo, float hi) {
    ull r; asm("mov.b64 %0, {%1, %2};" : "=l"(r) : "f"(lo), "f"(hi)); return r;
}
__device__ __forceinline__ float2 unpack2(ull v) {
    float2 r; asm("mov.b64 {%0, %1}, %2;" : "=f"(r.x), "=f"(r.y) : "l"(v)); return r;
}

// group barrier: 128 threads, named barrier id = group+1
#define GBAR(id) asm volatile("bar.sync %0, 128;" :: "r"(id) : "memory")

// ---------------------------------------------------------------------------
// Main: 128 blocks x 256 threads; two independent 128-thread groups per block
// (one batch each, named barriers). Batch assignment is LENGTH-SORT PAIRED:
// block k hosts (g_sched[k], g_sched[255-k]) -> the long batch's partner
// exits almost immediately, so the critical chain runs solo (1 warp/SMSP).
// Thread j owns column j of expT = exp(T) in 64 packed f32x2 registers.
// Per step: shift = lag-1 fs[0] (logsumexp shift-exact, drift << 88);
// p = exp(fs - m) -> smem; dot via 64 fma.rn.f32x2 in 8 chains;
// fs = e_t + m + log(dot). One bar.sync per step.
// ---------------------------------------------------------------------------
__global__ void __launch_bounds__(256, 1) crf_main(
    const float* __restrict__ emit,
    const int*   __restrict__ labels,
    const float* __restrict__ T,
    float* out)
{
    __shared__ __align__(16) float sm_p[2][2][CRF_L];   // [group][buf][i]
    __shared__ float sm_m[2][2];                        // [group][buf]
    __shared__ float sm_red[2][2][4];                   // final reduction scratch

    int tid  = threadIdx.x;
    int grp  = tid >> 7;            // 0 short-side, 1 long-side (higher wid = arbiter priority)
    int gt   = tid & 127;           // thread-in-group == column j
    int lane = tid & 31;
    int barid = grp + 1;

    int b   = grp ? g_sched[255 - blockIdx.x] : g_sched[blockIdx.x];
    int len = g_len[b];

    // ---- expT column j -> 64 packed register pairs ----
    ull mat[64];
    #pragma unroll
    for (int k = 0; k < 64; k++) {
        float lo = __expf(T[(2 * k)     * CRF_L + gt]);
        float hi = __expf(T[(2 * k + 1) * CRF_L + gt]);
        mat[k] = pack2(lo, hi);
    }

    // ---- gold path (warp 0 of each group) ----
    float gold = 0.f, ends = 0.f;
    if ((gt >> 5) == 0) {
        for (int t = lane; t < len; t += 32) {
            int lab  = labels[b * CRF_S + t];
            int prev = (t == 0) ? START_ID : labels[b * CRF_S + t - 1];
            gold += emit[((size_t)t * CRF_B + b) * CRF_L + lab] + T[prev * CRF_L + lab];
        }
        #pragma unroll
        for (int o = 16; o; o >>= 1) gold += __shfl_xor_sync(0xffffffffu, gold, o);
        ends = T[labels[b * CRF_S + (len - 1)] * CRF_L + PAD_ID];
    }

    // ---- init: fs_j = emit[0][b][j] + T[START][j]; shift = fs[0] (lag) ----
    float fs = emit[(size_t)b * CRF_L + gt] + T[START_ID * CRF_L + gt];
    if (gt == 0) sm_m[grp][0] = fs;
    GBAR(barid);
    float m = sm_m[grp][0];

    // ---- emit prefetch pipeline (depth 2) ----
    const long estride = (long)CRF_B * CRF_L;
    const float* ep = emit + estride + (size_t)b * CRF_L + gt;   // t=1
    float e_cur = 0.f, e_n = 0.f;
    if (len > 1) e_cur = ep[0];
    if (len > 2) e_n   = ep[estride];

    // ---- forward scan ----
    int buf = 1;
    for (int t = 1; t < len; t++) {
        float p = __expf(fs - m);
        sm_p[grp][buf][gt] = p;
        if (gt == 0) sm_m[grp][buf] = fs;

        float e_f = 0.f;
        if (t + 2 < len) e_f = ep[2 * estride];   // prefetch emit[t+2]

        GBAR(barid);

        float mN = sm_m[grp][buf];                // next-step shift (lag-1)

        // dot_j = sum_i p[i] * expT[i][j]  (64 packed FMA2, 8 chains)
        const ulonglong2* pb2 = reinterpret_cast<const ulonglong2*>(sm_p[grp][buf]);
        ull a0 = 0, a1 = 0, a2 = 0, a3 = 0, a4 = 0, a5 = 0, a6 = 0, a7 = 0;
        #pragma unroll
        for (int k = 0; k < 32; k += 4) {
            ulonglong2 pA = pb2[k];
            ulonglong2 pB = pb2[k + 1];
            ulonglong2 pC = pb2[k + 2];
            ulonglong2 pD = pb2[k + 3];
            a0 = fma2(pA.x, mat[2 * k],     a0);
            a1 = fma2(pA.y, mat[2 * k + 1], a1);
            a2 = fma2(pB.x, mat[2 * k + 2], a2);
            a3 = fma2(pB.y, mat[2 * k + 3], a3);
            a4 = fma2(pC.x, mat[2 * k + 4], a4);
            a5 = fma2(pC.y, mat[2 * k + 5], a5);
            a6 = fma2(pD.x, mat[2 * k + 6], a6);
            a7 = fma2(pD.y, mat[2 * k + 7], a7);
        }
        a0 = add2(a0, a1); a2 = add2(a2, a3); a4 = add2(a4, a5); a6 = add2(a6, a7);
        a0 = add2(a0, a2); a4 = add2(a4, a6);
        a0 = add2(a0, a4);
        float2 f0 = unpack2(a0);
        float dot = f0.x + f0.y;

        fs = e_cur + m + __logf(dot);

        m = mN;
        e_cur = e_n; e_n = e_f;
        ep += estride;
        buf ^= 1;
    }

    // ---- encode_b = logsumexp_j(fs[j] + T[j][PAD]) ----
    GBAR(barid);   // quiesce last iteration's smem traffic
    float x = fs + T[gt * CRF_L + PAD_ID];
    float wm = x;
    #pragma unroll
    for (int o = 16; o; o >>= 1) wm = fmaxf(wm, __shfl_xor_sync(0xffffffffu, wm, o));
    if (lane == 0) sm_red[grp][0][gt >> 5] = wm;
    GBAR(barid);
    float4 wv = *reinterpret_cast<float4*>(sm_red[grp][0]);
    float mm = fmaxf(fmaxf(wv.x, wv.y), fmaxf(wv.z, wv.w));
    float s = __expf(x - mm);
    #pragma unroll
    for (int o = 16; o; o >>= 1) s += __shfl_xor_sync(0xffffffffu, s, o);
    if (lane == 0) sm_red[grp][1][gt >> 5] = s;
    GBAR(barid);
    if (gt == 0) {
        float4 sv = *reinterpret_cast<float4*>(sm_red[grp][1]);
        float r = mm + __logf(sv.x + sv.y + sv.z + sv.w);
        atomicAdd(out, r - gold - ends);
    }
}

// ---------------------------------------------------------------------------
extern "C" void kernel_launch(void* const* d_in, const int* in_sizes, int n_in,
                              void* d_out, int out_size) {
    const float* emit   = (const float*)d_in[0];
    const int*   labels = (const int*)d_in[1];
    const void*  masks  = d_in[2];
    const float* T      = (const float*)d_in[3];
    float* out = (float*)d_out;

    (void)in_sizes; (void)n_in; (void)out_size;

    crf_prep<<<1, 256>>>(masks, out);
    crf_main<<<CRF_B / 2, 256>>>(emit, labels, T, out);
}

// round 14
// speedup vs baseline: 1.8973x; 1.1216x over previous
#include <cuda_runtime.h>
#include <cstdint>

#define CRF_S 512
#define CRF_B 256
#define CRF_L 128
#define PAD_ID 0
#define START_ID 1

typedef unsigned long long ull;

__device__ int g_mode;            // 0 = int32, 1 = byte, 2 = float32
__device__ int g_len[CRF_B];      // per-batch length
__device__ int g_sched[CRF_B];    // batch index sorted by length (ascending)

// ---------------------------------------------------------------------------
// Prep: detect mask dtype, compute all lengths, rank-sort batches, zero out.
// ---------------------------------------------------------------------------
__global__ void crf_prep(const void* __restrict__ masks, float* out) {
    __shared__ int flagByte, flagFloat;
    __shared__ int slen[CRF_B];
    int tid  = threadIdx.x;
    int wid  = tid >> 5;
    int lane = tid & 31;
    if (tid == 0) { flagByte = 0; flagFloat = 0; out[0] = 0.0f; }
    __syncthreads();

    const unsigned* mw = (const unsigned*)masks;
    int lb = 0, lf = 0;
    for (int k = tid; k < (CRF_B * CRF_S) / 4; k += 256) {
        unsigned w = mw[k];
        if (w == 0x3F800000u) lf = 1;          // float 1.0 pattern
        else if (w > 1u) lb = 1;               // byte-packed bools
    }
    if (lb) atomicOr(&flagByte, 1);
    if (lf) atomicOr(&flagFloat, 1);
    __syncthreads();
    int mode = flagFloat ? 2 : (flagByte ? 1 : 0);
    if (tid == 0) g_mode = mode;

    for (int b = wid; b < CRF_B; b += 8) {
        int cnt = 0;
        if (mode == 1) {
            const unsigned char* mb = (const unsigned char*)masks + (size_t)b * CRF_S;
            for (int k = lane; k < CRF_S; k += 32) cnt += (mb[k] != 0);
        } else if (mode == 2) {
            const float* mf = (const float*)masks + (size_t)b * CRF_S;
            for (int k = lane; k < CRF_S; k += 32) cnt += (mf[k] != 0.0f);
        } else {
            const int* mi = (const int*)masks + (size_t)b * CRF_S;
            for (int k = lane; k < CRF_S; k += 32) cnt += (mi[k] != 0);
        }
        #pragma unroll
        for (int o = 16; o; o >>= 1) cnt += __shfl_xor_sync(0xffffffffu, cnt, o);
        if (cnt < 1) cnt = 1;
        if (lane == 0) { slen[b] = cnt; g_len[b] = cnt; }
    }
    __syncthreads();

    int mylen = slen[tid];
    int rank = 0;
    for (int j = 0; j < CRF_B; j++) {
        int lj = slen[j];
        rank += (lj < mylen) || (lj == mylen && j < tid);
    }
    g_sched[rank] = tid;
}

// ---- packed f32x2 helpers ----
__device__ __forceinline__ ull fma2(ull a, ull b, ull c) {
    ull d;
    asm("fma.rn.f32x2 %0, %1, %2, %3;" : "=l"(d) : "l"(a), "l"(b), "l"(c));
    return d;
}
__device__ __forceinline__ ull add2(ull a, ull b) {
    ull d;
    asm("add.rn.f32x2 %0, %1, %2;" : "=l"(d) : "l"(a), "l"(b));
    return d;
}
__device__ __forceinline__ ull pack2(float lo, float hi) {
    ull r; asm("mov.b64 %0, {%1, %2};" : "=l"(r) : "f"(lo), "f"(hi)); return r;
}
__device__ __forceinline__ float2 unpack2(ull v) {
    float2 r; asm("mov.b64 {%0, %1}, %2;" : "=f"(r.x), "=f"(r.y) : "l"(v)); return r;
}
__device__ __forceinline__ float rcpf(float x) {
    float r; asm("rcp.approx.f32 %0, %1;" : "=f"(r) : "f"(x)); return r;
}

// group barrier: 128 threads, named barrier id = group+1
#define GBAR(id) asm volatile("bar.sync %0, 128;" :: "r"(id) : "memory")

// ---------------------------------------------------------------------------
// Main: 128 blocks x 256 threads; two independent 128-thread groups per block,
// LENGTH-SORT PAIRED (block k hosts g_sched[k] and g_sched[255-k]) so the
// critical (longest) batch runs solo on its SM for nearly its whole life.
// Thread j owns column j of expT = exp(T) in 64 packed f32x2 registers.
//
// Exp/log-free recurrence (identical numerics to shift m = lag-1 fs[0]):
//   p_t[j] = dot_j * exp(e_t[j]) * rcp(p_{t-1}[0])
//   M_t    = M_{t-1} + log(p_{t-1}[0])          (scalar, off critical path)
// where dot_j = sum_i p_{t-1}[i] * expT[i][j]. MUFU ops (exp of e, rcp, log)
// all issue early and hide inside the 64-FMA2 window. Critical chain per step
// is just BAR -> LDS -> FMA block -> tree -> mul -> STS.
// Final: encode_b = M + log( sum_j p[j] * exp(T[j][PAD]) ).
// ---------------------------------------------------------------------------
__global__ void __launch_bounds__(256, 1) crf_main(
    const float* __restrict__ emit,
    const int*   __restrict__ labels,
    const float* __restrict__ T,
    float* out)
{
    __shared__ __align__(16) float sm_p[2][2][CRF_L];   // [group][buf][i]
    __shared__ __align__(16) float sm_red[2][4];        // final reduction scratch
    __shared__ __align__(16) float sm_m0[2];            // init shift broadcast

    int tid  = threadIdx.x;
    int grp  = tid >> 7;            // 0 short-side, 1 long-side
    int gt   = tid & 127;           // thread-in-group == column j
    int lane = tid & 31;
    int barid = grp + 1;

    int b   = grp ? g_sched[255 - blockIdx.x] : g_sched[blockIdx.x];
    int len = g_len[b];

    // ---- expT column j -> 64 packed register pairs ----
    ull mat[64];
    #pragma unroll
    for (int k = 0; k < 64; k++) {
        float lo = __expf(T[(2 * k)     * CRF_L + gt]);
        float hi = __expf(T[(2 * k + 1) * CRF_L + gt]);
        mat[k] = pack2(lo, hi);
    }

    // ---- gold path (warp 0 of each group) ----
    float gold = 0.f, ends = 0.f;
    if ((gt >> 5) == 0) {
        for (int t = lane; t < len; t += 32) {
            int lab  = labels[b * CRF_S + t];
            int prev = (t == 0) ? START_ID : labels[b * CRF_S + t - 1];
            gold += emit[((size_t)t * CRF_B + b) * CRF_L + lab] + T[prev * CRF_L + lab];
        }
        #pragma unroll
        for (int o = 16; o; o >>= 1) gold += __shfl_xor_sync(0xffffffffu, gold, o);
        ends = T[labels[b * CRF_S + (len - 1)] * CRF_L + PAD_ID];
    }

    // ---- init: fs0_j = emit[0][b][j] + T[START][j]; M = fs0[0]; p0 = exp(fs0-M) ----
    float fs0 = emit[(size_t)b * CRF_L + gt] + T[START_ID * CRF_L + gt];
    if (gt == 0) sm_m0[grp] = fs0;
    GBAR(barid);
    float M = sm_m0[grp];
    float p = __expf(fs0 - M);
    sm_p[grp][0][gt] = p;

    // ---- emit prefetch pipeline (depth 2, raw values; exp applied in-loop) ----
    const long estride = (long)CRF_B * CRF_L;
    const float* ep = emit + estride + (size_t)b * CRF_L + gt;   // t=1
    float e_cur = 0.f, e_n = 0.f;
    if (len > 1) e_cur = ep[0];
    if (len > 2) e_n   = ep[estride];

    // ---- forward scan ----
    int buf = 0;   // buffer holding p_{t-1}
    for (int t = 1; t < len; t++) {
        GBAR(barid);

        float expE = __expf(e_cur);               // MUFU, hidden in FMA window

        const ulonglong2* pb2 = reinterpret_cast<const ulonglong2*>(sm_p[grp][buf]);
        ulonglong2 c0 = pb2[0];                   // contains p_prev[0] (low float)
        float p0prev = unpack2(c0.x).x;
        float r = rcpf(p0prev);                   // MUFU, hidden
        M += __logf(p0prev);                      // scalar tracker, hidden

        float e_f = 0.f;
        if (t + 2 < len) e_f = ep[2 * estride];   // prefetch emit[t+2]

        // dot_j = sum_i p[i] * expT[i][j]  (64 packed FMA2, 8 chains)
        ull a0, a1, a2, a3, a4, a5, a6, a7;
        {
            ulonglong2 pB = pb2[1];
            ulonglong2 pC = pb2[2];
            ulonglong2 pD = pb2[3];
            a0 = fma2(c0.x, mat[0], 0); a1 = fma2(c0.y, mat[1], 0);
            a2 = fma2(pB.x, mat[2], 0); a3 = fma2(pB.y, mat[3], 0);
            a4 = fma2(pC.x, mat[4], 0); a5 = fma2(pC.y, mat[5], 0);
            a6 = fma2(pD.x, mat[6], 0); a7 = fma2(pD.y, mat[7], 0);
        }
        #pragma unroll
        for (int k = 4; k < 32; k += 4) {
            ulonglong2 pA = pb2[k];
            ulonglong2 pB = pb2[k + 1];
            ulonglong2 pC = pb2[k + 2];
            ulonglong2 pD = pb2[k + 3];
            a0 = fma2(pA.x, mat[2 * k],     a0);
            a1 = fma2(pA.y, mat[2 * k + 1], a1);
            a2 = fma2(pB.x, mat[2 * k + 2], a2);
            a3 = fma2(pB.y, mat[2 * k + 3], a3);
            a4 = fma2(pC.x, mat[2 * k + 4], a4);
            a5 = fma2(pC.y, mat[2 * k + 5], a5);
            a6 = fma2(pD.x, mat[2 * k + 6], a6);
            a7 = fma2(pD.y, mat[2 * k + 7], a7);
        }
        a0 = add2(a0, a1); a2 = add2(a2, a3); a4 = add2(a4, a5); a6 = add2(a6, a7);
        a0 = add2(a0, a2); a4 = add2(a4, a6);
        a0 = add2(a0, a4);
        float2 f0 = unpack2(a0);
        float dot = f0.x + f0.y;

        p = dot * (expE * r);                     // exp/log-free p update
        sm_p[grp][buf ^ 1][gt] = p;

        e_cur = e_n; e_n = e_f;
        ep += estride;
        buf ^= 1;
    }

    // ---- encode_b = M + log( sum_j p[j] * exp(T[j][PAD]) ) ----
    float y = p * __expf(T[gt * CRF_L + PAD_ID]);
    #pragma unroll
    for (int o = 16; o; o >>= 1) y += __shfl_xor_sync(0xffffffffu, y, o);
    if (lane == 0) sm_red[grp][gt >> 5] = y;
    GBAR(barid);
    if (gt == 0) {
        float4 sv = *reinterpret_cast<float4*>(sm_red[grp]);
        float r2 = M + __logf(sv.x + sv.y + sv.z + sv.w);
        atomicAdd(out, r2 - gold - ends);
    }
}

// ---------------------------------------------------------------------------
extern "C" void kernel_launch(void* const* d_in, const int* in_sizes, int n_in,
                              void* d_out, int out_size) {
    const float* emit   = (const float*)d_in[0];
    const int*   labels = (const int*)d_in[1];
    const void*  masks  = d_in[2];
    const float* T      = (const float*)d_in[3];
    float* out = (float*)d_out;

    (void)in_sizes; (void)n_in; (void)out_size;

    crf_prep<<<1, 256>>>(masks, out);
    crf_main<<<CRF_B / 2, 256>>>(emit, labels, T, out);
}

// round 15
// speedup vs baseline: 2.1527x; 1.1346x over previous
#include <cuda_runtime.h>
#include <cuda_bf16.h>
#include <cstdint>

#define CRF_S 512
#define CRF_B 256
#define CRF_L 128
#define PAD_ID 0
#define START_ID 1

typedef unsigned long long ull;

__device__ int g_mode;            // 0 = int32, 1 = byte, 2 = float32
__device__ int g_len[CRF_B];      // per-batch length
__device__ int g_sched[CRF_B];    // batch index sorted by length (ascending)

// ---------------------------------------------------------------------------
// Prep: detect mask dtype, compute all lengths, rank-sort batches, zero out.
// ---------------------------------------------------------------------------
__global__ void crf_prep(const void* __restrict__ masks, float* out) {
    __shared__ int flagByte, flagFloat;
    __shared__ int slen[CRF_B];
    int tid  = threadIdx.x;
    int wid  = tid >> 5;
    int lane = tid & 31;
    if (tid == 0) { flagByte = 0; flagFloat = 0; out[0] = 0.0f; }
    __syncthreads();

    const unsigned* mw = (const unsigned*)masks;
    int lb = 0, lf = 0;
    for (int k = tid; k < (CRF_B * CRF_S) / 4; k += 256) {
        unsigned w = mw[k];
        if (w == 0x3F800000u) lf = 1;          // float 1.0 pattern
        else if (w > 1u) lb = 1;               // byte-packed bools
    }
    if (lb) atomicOr(&flagByte, 1);
    if (lf) atomicOr(&flagFloat, 1);
    __syncthreads();
    int mode = flagFloat ? 2 : (flagByte ? 1 : 0);
    if (tid == 0) g_mode = mode;

    for (int b = wid; b < CRF_B; b += 8) {
        int cnt = 0;
        if (mode == 1) {
            const unsigned char* mb = (const unsigned char*)masks + (size_t)b * CRF_S;
            for (int k = lane; k < CRF_S; k += 32) cnt += (mb[k] != 0);
        } else if (mode == 2) {
            const float* mf = (const float*)masks + (size_t)b * CRF_S;
            for (int k = lane; k < CRF_S; k += 32) cnt += (mf[k] != 0.0f);
        } else {
            const int* mi = (const int*)masks + (size_t)b * CRF_S;
            for (int k = lane; k < CRF_S; k += 32) cnt += (mi[k] != 0);
        }
        #pragma unroll
        for (int o = 16; o; o >>= 1) cnt += __shfl_xor_sync(0xffffffffu, cnt, o);
        if (cnt < 1) cnt = 1;
        if (lane == 0) { slen[b] = cnt; g_len[b] = cnt; }
    }
    __syncthreads();

    int mylen = slen[tid];
    int rank = 0;
    for (int j = 0; j < CRF_B; j++) {
        int lj = slen[j];
        rank += (lj < mylen) || (lj == mylen && j < tid);
    }
    g_sched[rank] = tid;
}

// ---- bf16x2 helpers ----
__device__ __forceinline__ unsigned bfma2(unsigned a, unsigned b, unsigned c) {
    unsigned d;
    asm("fma.rn.bf16x2 %0, %1, %2, %3;" : "=r"(d) : "r"(a), "r"(b), "r"(c));
    return d;
}
__device__ __forceinline__ unsigned badd2(unsigned a, unsigned b) {
    unsigned d;
    asm("add.rn.bf16x2 %0, %1, %2;" : "=r"(d) : "r"(a), "r"(b));
    return d;
}
__device__ __forceinline__ unsigned packbf2(float lo, float hi) {
    unsigned r;
    asm("cvt.rn.bf16x2.f32 %0, %1, %2;" : "=r"(r) : "f"(hi), "f"(lo));
    return r;
}
// unpack bf16x2 word -> two f32 (bf16 is truncated f32: shift into the top bits)
__device__ __forceinline__ float bf_lo(unsigned v) { return __uint_as_float(v << 16); }
__device__ __forceinline__ float bf_hi(unsigned v) { return __uint_as_float(v & 0xFFFF0000u); }

__device__ __forceinline__ float rcpf(float x) {
    float r; asm("rcp.approx.f32 %0, %1;" : "=f"(r) : "f"(x)); return r;
}

// group barrier: 128 threads, named barrier id = group+1
#define GBAR(id) asm volatile("bar.sync %0, 128;" :: "r"(id) : "memory")

// ---------------------------------------------------------------------------
// Main: 128 blocks x 256 threads; two independent 128-thread groups per block,
// LENGTH-SORT PAIRED (block k hosts g_sched[k] and g_sched[255-k]) so the
// critical (longest) batch runs solo on its SM for nearly its whole life.
// Thread j owns column j of expT = exp(T) as 64 packed bf16x2 registers.
//
// Exp/log-free recurrence (self-consistent under any rounding of stored p):
//   p_t[j] = dot_j * exp(e_t[j]) * rcp(p_{t-1}[0])
//   M_t    = M_{t-1} + log(p_{t-1}[0])          (scalar, off critical path)
// dot_j = sum_i p_{t-1}[i] * expT[i][j] in bf16 (HFMA2, rt2 = 2x fp32 MAC
// rate): 64 HFMA2 + 16 LDS.128 per thread per step. MUFU ops hidden in the
// FMA window. Final: encode_b = M + log( sum_j p[j] * exp(T[j][PAD]) ).
// ---------------------------------------------------------------------------
__global__ void __launch_bounds__(256, 1) crf_main(
    const float* __restrict__ emit,
    const int*   __restrict__ labels,
    const float* __restrict__ T,
    float* out)
{
    __shared__ __align__(16) __nv_bfloat16 sm_p[2][2][CRF_L];  // [group][buf][i]
    __shared__ __align__(16) float sm_red[2][4];               // reduction scratch
    __shared__ __align__(16) float sm_m0[2];                   // init shift broadcast

    int tid  = threadIdx.x;
    int grp  = tid >> 7;            // 0 short-side, 1 long-side
    int gt   = tid & 127;           // thread-in-group == column j
    int lane = tid & 31;
    int barid = grp + 1;

    int b   = grp ? g_sched[255 - blockIdx.x] : g_sched[blockIdx.x];
    int len = g_len[b];

    // ---- expT column j -> 64 packed bf16x2 registers ----
    unsigned mat[64];
    #pragma unroll
    for (int k = 0; k < 64; k++) {
        float lo = __expf(T[(2 * k)     * CRF_L + gt]);
        float hi = __expf(T[(2 * k + 1) * CRF_L + gt]);
        mat[k] = packbf2(lo, hi);
    }

    // ---- gold path (warp 0 of each group) ----
    float gold = 0.f, ends = 0.f;
    if ((gt >> 5) == 0) {
        for (int t = lane; t < len; t += 32) {
            int lab  = labels[b * CRF_S + t];
            int prev = (t == 0) ? START_ID : labels[b * CRF_S + t - 1];
            gold += emit[((size_t)t * CRF_B + b) * CRF_L + lab] + T[prev * CRF_L + lab];
        }
        #pragma unroll
        for (int o = 16; o; o >>= 1) gold += __shfl_xor_sync(0xffffffffu, gold, o);
        ends = T[labels[b * CRF_S + (len - 1)] * CRF_L + PAD_ID];
    }

    // ---- init: fs0_j = emit[0][b][j] + T[START][j]; M = fs0[0]; p0 = exp(fs0-M) ----
    float fs0 = emit[(size_t)b * CRF_L + gt] + T[START_ID * CRF_L + gt];
    if (gt == 0) sm_m0[grp] = fs0;
    GBAR(barid);
    float M = sm_m0[grp];
    float p = __expf(fs0 - M);
    sm_p[grp][0][gt] = __float2bfloat16(p);

    // ---- emit prefetch pipeline (depth 2, raw values) ----
    const long estride = (long)CRF_B * CRF_L;
    const float* ep = emit + estride + (size_t)b * CRF_L + gt;   // t=1
    float e_cur = 0.f, e_n = 0.f;
    if (len > 1) e_cur = ep[0];
    if (len > 2) e_n   = ep[estride];

    // ---- forward scan ----
    int buf = 0;   // buffer holding p_{t-1}
    for (int t = 1; t < len; t++) {
        GBAR(barid);

        float expE = __expf(e_cur);               // MUFU, hidden in FMA window

        const uint4* pb4 = reinterpret_cast<const uint4*>(sm_p[grp][buf]);
        uint4 q0 = pb4[0];                        // p[0..7]; p_prev[0] = low bf16 of q0.x
        float p0prev = bf_lo(q0.x);
        float r = rcpf(p0prev);                   // MUFU, hidden
        M += __logf(p0prev);                      // scalar tracker, hidden

        float e_f = 0.f;
        if (t + 2 < len) e_f = ep[2 * estride];   // prefetch emit[t+2]

        // dot_j = sum_i p[i] * expT[i][j]  (64 HFMA2, 8 chains, 16 LDS.128)
        unsigned a0, a1, a2, a3, a4, a5, a6, a7;
        {
            uint4 qB = pb4[1];
            a0 = bfma2(q0.x, mat[0], 0u); a1 = bfma2(q0.y, mat[1], 0u);
            a2 = bfma2(q0.z, mat[2], 0u); a3 = bfma2(q0.w, mat[3], 0u);
            a4 = bfma2(qB.x, mat[4], 0u); a5 = bfma2(qB.y, mat[5], 0u);
            a6 = bfma2(qB.z, mat[6], 0u); a7 = bfma2(qB.w, mat[7], 0u);
        }
        #pragma unroll
        for (int k = 2; k < 16; k += 2) {
            uint4 qA = pb4[k];
            uint4 qB = pb4[k + 1];
            a0 = bfma2(qA.x, mat[4 * k],     a0);
            a1 = bfma2(qA.y, mat[4 * k + 1], a1);
            a2 = bfma2(qA.z, mat[4 * k + 2], a2);
            a3 = bfma2(qA.w, mat[4 * k + 3], a3);
            a4 = bfma2(qB.x, mat[4 * k + 4], a4);
            a5 = bfma2(qB.y, mat[4 * k + 5], a5);
            a6 = bfma2(qB.z, mat[4 * k + 6], a6);
            a7 = bfma2(qB.w, mat[4 * k + 7], a7);
        }
        // 8 -> 4 chains in bf16, then exact f32 tree
        a0 = badd2(a0, a1); a2 = badd2(a2, a3);
        a4 = badd2(a4, a5); a6 = badd2(a6, a7);
        float dot = ((bf_lo(a0) + bf_hi(a0)) + (bf_lo(a2) + bf_hi(a2)))
                  + ((bf_lo(a4) + bf_hi(a4)) + (bf_lo(a6) + bf_hi(a6)));

        p = dot * (expE * r);                     // exp/log-free p update
        sm_p[grp][buf ^ 1][gt] = __float2bfloat16(p);

        e_cur = e_n; e_n = e_f;
        ep += estride;
        buf ^= 1;
    }

    // ---- encode_b = M + log( sum_j p[j] * exp(T[j][PAD]) ) ----
    float y = p * __expf(T[gt * CRF_L + PAD_ID]);
    #pragma unroll
    for (int o = 16; o; o >>= 1) y += __shfl_xor_sync(0xffffffffu, y, o);
    if (lane == 0) sm_red[grp][gt >> 5] = y;
    GBAR(barid);
    if (gt == 0) {
        float4 sv = *reinterpret_cast<float4*>(sm_red[grp]);
        float r2 = M + __logf(sv.x + sv.y + sv.z + sv.w);
        atomicAdd(out, r2 - gold - ends);
    }
}

// ---------------------------------------------------------------------------
extern "C" void kernel_launch(void* const* d_in, const int* in_sizes, int n_in,
                              void* d_out, int out_size) {
    const float* emit   = (const float*)d_in[0];
    const int*   labels = (const int*)d_in[1];
    const void*  masks  = d_in[2];
    const float* T      = (const float*)d_in[3];
    float* out = (float*)d_out;

    (void)in_sizes; (void)n_in; (void)out_size;

    crf_prep<<<1, 256>>>(masks, out);
    crf_main<<<CRF_B / 2, 256>>>(emit, labels, T, out);
}